// round 9
// baseline (speedup 1.0000x reference)
#include <cuda_runtime.h>
#include <cuda_fp16.h>
#include <cstdint>

#define MAX_N 50000
#define MAX_E 800000
#define IN_C  256
#define HID   128
#define OUTC  64
#define SCAN_B 256
#define SCAN_NBLK ((MAX_N + SCAN_B - 1) / SCAN_B)   // 196

// ---- scratch (device globals: no allocations allowed) ----
__device__ int    g_is64;
__device__ int    g_csr[MAX_E];         // src indices grouped by dst
__device__ int    g_cnt[MAX_N];         // in-degree (excl self loop)
__device__ int    g_start[MAX_N];       // CSR row start
__device__ int    g_cursor[MAX_N];
__device__ int    g_bsum[SCAN_NBLK];
__device__ float  g_dis[MAX_N];
__device__ __half g_hs1[MAX_N * HID];   // UNSCALED layer-1 GEMM output (f16)
__device__ __half g_act1[MAX_N * HID];  // relu'd layer-1 output (f16, GEMM2 input)
__device__ __half g_hs2[MAX_N * OUTC];  // dis-scaled layer-2 GEMM output (f16)

// ---------------- CSR build ----------------
__global__ void k_zero_detect(const long long* __restrict__ ei, int n) {
    int i = blockIdx.x * blockDim.x + threadIdx.x;
    if (i < n) g_cnt[i] = 0;
    if (blockIdx.x == 0) {
        __shared__ int ok;
        if (threadIdx.x == 0) ok = 1;
        __syncthreads();
        long long v = ei[threadIdx.x];
        if (v < 0 || v >= MAX_N) ok = 0;
        __syncthreads();
        if (threadIdx.x == 0) g_is64 = ok;
    }
}

// 4 edges per thread (vectorized int32 fast path)
__global__ void k_hist(const void* __restrict__ ei, int E) {
    int i4 = (blockIdx.x * blockDim.x + threadIdx.x) * 4;
    if (i4 >= E) return;
    if (!g_is64 && i4 + 4 <= E) {
        int4 d = *reinterpret_cast<const int4*>((const int*)ei + E + i4);
        atomicAdd(&g_cnt[d.x], 1);
        atomicAdd(&g_cnt[d.y], 1);
        atomicAdd(&g_cnt[d.z], 1);
        atomicAdd(&g_cnt[d.w], 1);
    } else {
        for (int i = i4; i < min(i4 + 4, E); i++) {
            int d = g_is64 ? (int)((const long long*)ei)[i + E]
                           : ((const int*)ei)[i + E];
            atomicAdd(&g_cnt[d], 1);
        }
    }
}

__global__ void k_scan1(int n) {
    __shared__ int s[SCAN_B];
    int i = blockIdx.x * SCAN_B + threadIdx.x;
    int v = (i < n) ? g_cnt[i] : 0;
    s[threadIdx.x] = v;
    __syncthreads();
#pragma unroll
    for (int off = 1; off < SCAN_B; off <<= 1) {
        int x = (threadIdx.x >= off) ? s[threadIdx.x - off] : 0;
        __syncthreads();
        s[threadIdx.x] += x;
        __syncthreads();
    }
    if (i < n) g_start[i] = s[threadIdx.x] - v;   // exclusive within block
    if (threadIdx.x == SCAN_B - 1) g_bsum[blockIdx.x] = s[SCAN_B - 1];
}

// scan2 folded in: every block redundantly scans the 196 block sums in smem
__global__ void k_scan3(int n, int nblk) {
    __shared__ int s[SCAN_B];
    int v = (threadIdx.x < nblk) ? g_bsum[threadIdx.x] : 0;
    s[threadIdx.x] = v;
    __syncthreads();
#pragma unroll
    for (int off = 1; off < SCAN_B; off <<= 1) {
        int x = (threadIdx.x >= off) ? s[threadIdx.x - off] : 0;
        __syncthreads();
        s[threadIdx.x] += x;
        __syncthreads();
    }
    int boff = (blockIdx.x == 0) ? 0 : s[blockIdx.x - 1];   // inclusive scan -> exclusive
    int i = blockIdx.x * SCAN_B + threadIdx.x;
    if (i >= n) return;
    int st = g_start[i] + boff;
    g_start[i]  = st;
    g_cursor[i] = st;
    g_dis[i]    = rsqrtf((float)(g_cnt[i] + 1));
}

// 4 edges per thread (vectorized int32 fast path)
__global__ void k_fill(const void* __restrict__ ei, int E) {
    int i4 = (blockIdx.x * blockDim.x + threadIdx.x) * 4;
    if (i4 >= E) return;
    if (!g_is64 && i4 + 4 <= E) {
        int4 sv = *reinterpret_cast<const int4*>((const int*)ei + i4);
        int4 dv = *reinterpret_cast<const int4*>((const int*)ei + E + i4);
        g_csr[atomicAdd(&g_cursor[dv.x], 1)] = sv.x;
        g_csr[atomicAdd(&g_cursor[dv.y], 1)] = sv.y;
        g_csr[atomicAdd(&g_cursor[dv.z], 1)] = sv.z;
        g_csr[atomicAdd(&g_cursor[dv.w], 1)] = sv.w;
    } else {
        for (int i = i4; i < min(i4 + 4, E); i++) {
            int sIdx, d;
            if (g_is64) {
                const long long* p = (const long long*)ei;
                sIdx = (int)p[i]; d = (int)p[i + E];
            } else {
                const int* p = (const int*)ei;
                sIdx = p[i]; d = p[i + E];
            }
            g_csr[atomicAdd(&g_cursor[d], 1)] = sIdx;
        }
    }
}

// ---------------- split-tf32 tensor-core GEMM ----------------
__device__ __forceinline__ void cvt_split(float x, unsigned& hi, unsigned& lo) {
    asm("cvt.rna.tf32.f32 %0, %1;" : "=r"(hi) : "f"(x));
    float l = x - __uint_as_float(hi);
    asm("cvt.rna.tf32.f32 %0, %1;" : "=r"(lo) : "f"(l));
}

__device__ __forceinline__ void mma8(float* c, const unsigned* a, const unsigned* b) {
    asm volatile(
        "mma.sync.aligned.m16n8k8.row.col.f32.tf32.tf32.f32 "
        "{%0,%1,%2,%3},{%4,%5,%6,%7},{%8,%9},{%0,%1,%2,%3};"
        : "+f"(c[0]), "+f"(c[1]), "+f"(c[2]), "+f"(c[3])
        : "r"(a[0]), "r"(a[1]), "r"(a[2]), "r"(a[3]), "r"(b[0]), "r"(b[1]));
}

// out[row,col] = (SCALE ? dis[row] : 1) * (A[row,:] @ W[:,col]), stored as f16.
// AHALF: A is f16 (exact in tf32 -> no A-lo correction, 2 MMAs instead of 3).
template<int BN, bool SCALE, bool AHALF>
__global__ void __launch_bounds__(256)
gemm_tf32(const void* __restrict__ Av, const float* __restrict__ W,
          __half* __restrict__ out, int M, int K)
{
    constexpr int BM = 128, BK = 16;
    constexpr int LDA = BK + 4;
    constexpr int LDB = BN + 8;
    constexpr int NF  = BN / 16;
    constexpr int F4PR = BN / 4;
    constexpr int B_ITERS = (BK * F4PR) / 256;

    __shared__ unsigned As_hi[BM * LDA];
    __shared__ unsigned As_lo[AHALF ? 1 : BM * LDA];
    __shared__ unsigned Bs_hi[BK * LDB], Bs_lo[BK * LDB];

    const int tid  = threadIdx.x;
    const int lane = tid & 31, warp = tid >> 5;
    const int wm = warp & 3, wn = warp >> 2;   // 4 x 2 warp grid
    const int row0 = blockIdx.x * BM;

    float acc[2][NF][4];
#pragma unroll
    for (int mf = 0; mf < 2; mf++)
#pragma unroll
        for (int nf = 0; nf < NF; nf++)
#pragma unroll
            for (int j = 0; j < 4; j++) acc[mf][nf][j] = 0.0f;

    for (int kk = 0; kk < K; kk += BK) {
        if (AHALF) {
            const __half* A = (const __half*)Av;
            int r = tid >> 1, c = (tid & 1) * 8;
            uint4 v = make_uint4(0, 0, 0, 0);
            if (row0 + r < M)
                v = *reinterpret_cast<const uint4*>(A + (size_t)(row0 + r) * K + kk + c);
            const __half2* hp = reinterpret_cast<const __half2*>(&v);
#pragma unroll
            for (int j = 0; j < 4; j++) {
                float2 f = __half22float2(hp[j]);
                As_hi[r*LDA + c + 2*j    ] = __float_as_uint(f.x);  // exact tf32
                As_hi[r*LDA + c + 2*j + 1] = __float_as_uint(f.y);
            }
        } else {
            const float* A = (const float*)Av;
#pragma unroll
            for (int i = 0; i < 2; i++) {
                int flat = tid + i * 256;
                int r = flat >> 2, c = (flat & 3) * 4;
                float4 v = make_float4(0.f, 0.f, 0.f, 0.f);
                if (row0 + r < M)
                    v = *reinterpret_cast<const float4*>(A + (size_t)(row0 + r) * K + kk + c);
                unsigned h, l;
                cvt_split(v.x, h, l); As_hi[r*LDA + c    ] = h; As_lo[r*LDA + c    ] = l;
                cvt_split(v.y, h, l); As_hi[r*LDA + c + 1] = h; As_lo[r*LDA + c + 1] = l;
                cvt_split(v.z, h, l); As_hi[r*LDA + c + 2] = h; As_lo[r*LDA + c + 2] = l;
                cvt_split(v.w, h, l); As_hi[r*LDA + c + 3] = h; As_lo[r*LDA + c + 3] = l;
            }
        }
#pragma unroll
        for (int i = 0; i < B_ITERS; i++) {
            int flat = tid + i * 256;
            int r = flat / F4PR, c = (flat % F4PR) * 4;
            float4 v = *reinterpret_cast<const float4*>(W + (size_t)(kk + r) * BN + c);
            unsigned h, l;
            cvt_split(v.x, h, l); Bs_hi[r*LDB + c    ] = h; Bs_lo[r*LDB + c    ] = l;
            cvt_split(v.y, h, l); Bs_hi[r*LDB + c + 1] = h; Bs_lo[r*LDB + c + 1] = l;
            cvt_split(v.z, h, l); Bs_hi[r*LDB + c + 2] = h; Bs_lo[r*LDB + c + 2] = l;
            cvt_split(v.w, h, l); Bs_hi[r*LDB + c + 3] = h; Bs_lo[r*LDB + c + 3] = l;
        }
        __syncthreads();

#pragma unroll
        for (int ks = 0; ks < 2; ks++) {
            const int k0 = ks * 8;
            unsigned ah[2][4], al[2][4];
#pragma unroll
            for (int mf = 0; mf < 2; mf++) {
                int r = wm * 32 + mf * 16 + (lane >> 2);
                int c = k0 + (lane & 3);
                ah[mf][0] = As_hi[ r      * LDA + c    ];
                ah[mf][1] = As_hi[(r + 8) * LDA + c    ];
                ah[mf][2] = As_hi[ r      * LDA + c + 4];
                ah[mf][3] = As_hi[(r + 8) * LDA + c + 4];
                if (!AHALF) {
                    al[mf][0] = As_lo[ r      * LDA + c    ];
                    al[mf][1] = As_lo[(r + 8) * LDA + c    ];
                    al[mf][2] = As_lo[ r      * LDA + c + 4];
                    al[mf][3] = As_lo[(r + 8) * LDA + c + 4];
                }
            }
#pragma unroll
            for (int nf = 0; nf < NF; nf++) {
                int n = wn * (BN / 2) + nf * 8 + (lane >> 2);
                int kb = k0 + (lane & 3);
                unsigned bh[2], bl[2];
                bh[0] = Bs_hi[ kb      * LDB + n];
                bh[1] = Bs_hi[(kb + 4) * LDB + n];
                bl[0] = Bs_lo[ kb      * LDB + n];
                bl[1] = Bs_lo[(kb + 4) * LDB + n];
#pragma unroll
                for (int mf = 0; mf < 2; mf++) {
                    mma8(acc[mf][nf], ah[mf], bh);
                    mma8(acc[mf][nf], ah[mf], bl);
                    if (!AHALF) mma8(acc[mf][nf], al[mf], bh);
                }
            }
        }
        __syncthreads();
    }

#pragma unroll
    for (int mf = 0; mf < 2; mf++) {
        int r0 = row0 + wm * 32 + mf * 16 + (lane >> 2);
        int r1 = r0 + 8;
        float d0 = 1.f, d1 = 1.f;
        if (SCALE) {
            d0 = (r0 < M) ? g_dis[r0] : 0.f;
            d1 = (r1 < M) ? g_dis[r1] : 0.f;
        }
#pragma unroll
        for (int nf = 0; nf < NF; nf++) {
            int c = wn * (BN / 2) + nf * 8 + (lane & 3) * 2;
            if (r0 < M)
                *reinterpret_cast<__half2*>(out + (size_t)r0 * BN + c) =
                    __floats2half2_rn(acc[mf][nf][0] * d0, acc[mf][nf][1] * d0);
            if (r1 < M)
                *reinterpret_cast<__half2*>(out + (size_t)r1 * BN + c) =
                    __floats2half2_rn(acc[mf][nf][2] * d1, acc[mf][nf][3] * d1);
        }
    }
}

// ---------------- gather aggregation (f16 rows, f32 accumulate) ----------------
__device__ __forceinline__ void acch(float* a, uint2 v, float s) {
    __half2 h0 = *reinterpret_cast<__half2*>(&v.x);
    __half2 h1 = *reinterpret_cast<__half2*>(&v.y);
    float2 f0 = __half22float2(h0), f1 = __half22float2(h1);
    a[0] = fmaf(s, f0.x, a[0]);
    a[1] = fmaf(s, f0.y, a[1]);
    a[2] = fmaf(s, f1.x, a[2]);
    a[3] = fmaf(s, f1.y, a[3]);
}

__device__ __forceinline__ void acch2(float* a, unsigned v, float s) {
    float2 f = __half22float2(*reinterpret_cast<__half2*>(&v));
    a[0] = fmaf(s, f.x, a[0]);
    a[1] = fmaf(s, f.y, a[1]);
}

// layer 1: hs UNSCALED f16 [N,128]; act1 = f16(relu(dis[w]*(sum dis[s]*hs[s]) + b1))
// one warp per node, 8B per lane (256B row)
__global__ void k_agg128(const __half* __restrict__ hs, __half* __restrict__ out,
                         const float* __restrict__ bias, int N)
{
    int w = (blockIdx.x * blockDim.x + threadIdx.x) >> 5;
    if (w >= N) return;
    int lane = threadIdx.x & 31;
    const uint2* base = (const uint2*)hs;   // 32 uint2 per row

    int beg = g_start[w], cnt = g_cnt[w];
    float dw = g_dis[w];
    float a[4] = {0.f, 0.f, 0.f, 0.f};
    acch(a, base[(size_t)w * 32 + lane], dw);   // self loop

    int e = 0;
    for (; e + 8 <= cnt; e += 8) {
        int s0 = g_csr[beg+e  ], s1 = g_csr[beg+e+1], s2 = g_csr[beg+e+2], s3 = g_csr[beg+e+3];
        int s4 = g_csr[beg+e+4], s5 = g_csr[beg+e+5], s6 = g_csr[beg+e+6], s7 = g_csr[beg+e+7];
        uint2 v0 = base[(size_t)s0*32+lane], v1 = base[(size_t)s1*32+lane];
        uint2 v2 = base[(size_t)s2*32+lane], v3 = base[(size_t)s3*32+lane];
        uint2 v4 = base[(size_t)s4*32+lane], v5 = base[(size_t)s5*32+lane];
        uint2 v6 = base[(size_t)s6*32+lane], v7 = base[(size_t)s7*32+lane];
        acch(a, v0, g_dis[s0]); acch(a, v1, g_dis[s1]);
        acch(a, v2, g_dis[s2]); acch(a, v3, g_dis[s3]);
        acch(a, v4, g_dis[s4]); acch(a, v5, g_dis[s5]);
        acch(a, v6, g_dis[s6]); acch(a, v7, g_dis[s7]);
    }
    for (; e < cnt; e++) {
        int s = g_csr[beg + e];
        acch(a, base[(size_t)s*32+lane], g_dis[s]);
    }

    float4 b = ((const float4*)bias)[lane];
    uint2 r;
    __half2 r0 = __floats2half2_rn(fmaxf(fmaf(dw, a[0], b.x), 0.f),
                                   fmaxf(fmaf(dw, a[1], b.y), 0.f));
    __half2 r1 = __floats2half2_rn(fmaxf(fmaf(dw, a[2], b.z), 0.f),
                                   fmaxf(fmaf(dw, a[3], b.w), 0.f));
    r.x = *reinterpret_cast<unsigned*>(&r0);
    r.y = *reinterpret_cast<unsigned*>(&r1);
    ((uint2*)out)[(size_t)w * 32 + lane] = r;
}

// layer 2: hs dis-SCALED f16 [N,64]; out = dis[w]*(sum hs[s]) + b2 (f32)
// one warp per node, 4B (half2) per lane -> 128B row, no intra-warp divergence
__global__ void k_agg64(const __half* __restrict__ hs, float* __restrict__ out,
                        const float* __restrict__ bias, int N)
{
    int node = (blockIdx.x * blockDim.x + threadIdx.x) >> 5;
    if (node >= N) return;
    int lane = threadIdx.x & 31;
    const unsigned* base = (const unsigned*)hs;   // 32 half2 per row

    int beg = g_start[node], cnt = g_cnt[node];
    float a[2] = {0.f, 0.f};
    acch2(a, base[(size_t)node * 32 + lane], 1.f);   // self loop (already scaled)

    int e = 0;
    for (; e + 8 <= cnt; e += 8) {
        int s0 = g_csr[beg+e  ], s1 = g_csr[beg+e+1], s2 = g_csr[beg+e+2], s3 = g_csr[beg+e+3];
        int s4 = g_csr[beg+e+4], s5 = g_csr[beg+e+5], s6 = g_csr[beg+e+6], s7 = g_csr[beg+e+7];
        unsigned v0 = base[(size_t)s0*32+lane], v1 = base[(size_t)s1*32+lane];
        unsigned v2 = base[(size_t)s2*32+lane], v3 = base[(size_t)s3*32+lane];
        unsigned v4 = base[(size_t)s4*32+lane], v5 = base[(size_t)s5*32+lane];
        unsigned v6 = base[(size_t)s6*32+lane], v7 = base[(size_t)s7*32+lane];
        acch2(a, v0, 1.f); acch2(a, v1, 1.f); acch2(a, v2, 1.f); acch2(a, v3, 1.f);
        acch2(a, v4, 1.f); acch2(a, v5, 1.f); acch2(a, v6, 1.f); acch2(a, v7, 1.f);
    }
    for (; e < cnt; e++)
        acch2(a, base[(size_t)g_csr[beg+e]*32+lane], 1.f);

    float dw = g_dis[node];
    float2 b = ((const float2*)bias)[lane];
    float2 r;
    r.x = fmaf(dw, a[0], b.x);
    r.y = fmaf(dw, a[1], b.y);
    ((float2*)out)[(size_t)node * 32 + lane] = r;
}

// ---------------- launch ----------------
extern "C" void kernel_launch(void* const* d_in, const int* in_sizes, int n_in,
                              void* d_out, int out_size)
{
    const float* x   = (const float*)d_in[0];
    const void*  ei  = d_in[1];
    const float* W1  = (const float*)d_in[2];
    const float* b1  = (const float*)d_in[3];
    const float* W2  = (const float*)d_in[4];
    const float* b2  = (const float*)d_in[5];
    float*       out = (float*)d_out;

    const int N = in_sizes[0] / IN_C;   // 50000
    const int E = in_sizes[1] / 2;      // 800000
    const int nscan = (N + SCAN_B - 1) / SCAN_B;
    const int e4blocks = ((E + 3) / 4 + 255) / 256;

    __half *p_hs1, *p_act1, *p_hs2;
    cudaGetSymbolAddress((void**)&p_hs1,  g_hs1);
    cudaGetSymbolAddress((void**)&p_act1, g_act1);
    cudaGetSymbolAddress((void**)&p_hs2,  g_hs2);

    // one-time side stream + events for fork/join
    static cudaStream_t s2 = nullptr;
    static cudaEvent_t evFork = nullptr, evJoin = nullptr;
    if (!s2) {
        if (cudaStreamCreateWithFlags(&s2, cudaStreamNonBlocking) != cudaSuccess) s2 = nullptr;
        if (s2) {
            cudaEventCreateWithFlags(&evFork, cudaEventDisableTiming);
            cudaEventCreateWithFlags(&evJoin, cudaEventDisableTiming);
        }
    }

    // ---- fork: GEMM1 (independent of graph structure) on side stream ----
    bool forked = false;
    if (s2) {
        cudaEventRecord(evFork, 0);
        cudaStreamWaitEvent(s2, evFork, 0);
        gemm_tf32<HID, false, false><<<(N + 127) / 128, 256, 0, s2>>>(x, W1, p_hs1, N, IN_C);
        cudaEventRecord(evJoin, s2);
        forked = true;
    }

    // ---- main stream: CSR build + dis ----
    k_zero_detect<<<(N + 255) / 256, 256>>>((const long long*)ei, N);
    k_hist<<<e4blocks, 256>>>(ei, E);
    k_scan1<<<nscan, SCAN_B>>>(N);
    k_scan3<<<nscan, SCAN_B>>>(N, nscan);
    k_fill<<<e4blocks, 256>>>(ei, E);

    if (forked) cudaStreamWaitEvent(0, evJoin, 0);
    else        gemm_tf32<HID, false, false><<<(N + 127) / 128, 256>>>(x, W1, p_hs1, N, IN_C);

    // ---- layer 1 aggregate (+dis both sides, bias, relu) -> f16 act1 ----
    k_agg128<<<(N * 32 + 255) / 256, 256>>>(p_hs1, p_act1, b1, N);

    // ---- layer 2 GEMM (f16 A, exact tf32, 2 MMAs, dis-scaled) + aggregate ----
    gemm_tf32<OUTC, true, true><<<(N + 127) / 128, 256>>>(p_act1, W2, p_hs2, N, HID);
    k_agg64<<<(N * 32 + 255) / 256, 256>>>(p_hs2, out, b2, N);
}

// round 10
// speedup vs baseline: 1.0017x; 1.0017x over previous
#include <cuda_runtime.h>
#include <cuda_fp16.h>
#include <cstdint>

#define MAX_N 50000
#define MAX_E 800000
#define IN_C  256
#define HID   128
#define OUTC  64
#define SCAN_B 256
#define SCAN_NBLK ((MAX_N + SCAN_B - 1) / SCAN_B)   // 196

// ---- scratch (device globals: no allocations allowed) ----
__device__ int    g_is64;
__device__ int    g_csr[MAX_E];         // src indices grouped by dst
__device__ int    g_cnt[MAX_N];         // in-degree (excl self loop)
__device__ int    g_start[MAX_N];       // CSR row start
__device__ int    g_cursor[MAX_N];
__device__ int    g_bsum[SCAN_NBLK];
__device__ float  g_dis[MAX_N];
__device__ __half g_hs1[MAX_N * HID];   // UNSCALED layer-1 GEMM output (f16)
__device__ __half g_act1[MAX_N * HID];  // relu'd layer-1 output (f16, GEMM2 input)
__device__ __half g_hs2[MAX_N * OUTC];  // dis-scaled layer-2 GEMM output (f16)

// ---------------- CSR build ----------------
__global__ void k_zero_detect(const long long* __restrict__ ei, int n) {
    int i = blockIdx.x * blockDim.x + threadIdx.x;
    if (i < n) g_cnt[i] = 0;
    if (blockIdx.x == 0) {
        __shared__ int ok;
        if (threadIdx.x == 0) ok = 1;
        __syncthreads();
        long long v = ei[threadIdx.x];
        if (v < 0 || v >= MAX_N) ok = 0;
        __syncthreads();
        if (threadIdx.x == 0) g_is64 = ok;
    }
}

__global__ void k_hist(const void* __restrict__ ei, int E) {
    int i4 = (blockIdx.x * blockDim.x + threadIdx.x) * 4;
    if (i4 >= E) return;
    if (!g_is64 && i4 + 4 <= E) {
        int4 d = *reinterpret_cast<const int4*>((const int*)ei + E + i4);
        atomicAdd(&g_cnt[d.x], 1);
        atomicAdd(&g_cnt[d.y], 1);
        atomicAdd(&g_cnt[d.z], 1);
        atomicAdd(&g_cnt[d.w], 1);
    } else {
        for (int i = i4; i < min(i4 + 4, E); i++) {
            int d = g_is64 ? (int)((const long long*)ei)[i + E]
                           : ((const int*)ei)[i + E];
            atomicAdd(&g_cnt[d], 1);
        }
    }
}

__global__ void k_scan1(int n) {
    __shared__ int s[SCAN_B];
    int i = blockIdx.x * SCAN_B + threadIdx.x;
    int v = (i < n) ? g_cnt[i] : 0;
    s[threadIdx.x] = v;
    __syncthreads();
#pragma unroll
    for (int off = 1; off < SCAN_B; off <<= 1) {
        int x = (threadIdx.x >= off) ? s[threadIdx.x - off] : 0;
        __syncthreads();
        s[threadIdx.x] += x;
        __syncthreads();
    }
    if (i < n) g_start[i] = s[threadIdx.x] - v;
    if (threadIdx.x == SCAN_B - 1) g_bsum[blockIdx.x] = s[SCAN_B - 1];
}

// scan2 folded in: every block redundantly scans the 196 block sums in smem
__global__ void k_scan3(int n, int nblk) {
    __shared__ int s[SCAN_B];
    int v = (threadIdx.x < nblk) ? g_bsum[threadIdx.x] : 0;
    s[threadIdx.x] = v;
    __syncthreads();
#pragma unroll
    for (int off = 1; off < SCAN_B; off <<= 1) {
        int x = (threadIdx.x >= off) ? s[threadIdx.x - off] : 0;
        __syncthreads();
        s[threadIdx.x] += x;
        __syncthreads();
    }
    int boff = (blockIdx.x == 0) ? 0 : s[blockIdx.x - 1];
    int i = blockIdx.x * SCAN_B + threadIdx.x;
    if (i >= n) return;
    int st = g_start[i] + boff;
    g_start[i]  = st;
    g_cursor[i] = st;
    g_dis[i]    = rsqrtf((float)(g_cnt[i] + 1));
}

__global__ void k_fill(const void* __restrict__ ei, int E) {
    int i4 = (blockIdx.x * blockDim.x + threadIdx.x) * 4;
    if (i4 >= E) return;
    if (!g_is64 && i4 + 4 <= E) {
        int4 sv = *reinterpret_cast<const int4*>((const int*)ei + i4);
        int4 dv = *reinterpret_cast<const int4*>((const int*)ei + E + i4);
        g_csr[atomicAdd(&g_cursor[dv.x], 1)] = sv.x;
        g_csr[atomicAdd(&g_cursor[dv.y], 1)] = sv.y;
        g_csr[atomicAdd(&g_cursor[dv.z], 1)] = sv.z;
        g_csr[atomicAdd(&g_cursor[dv.w], 1)] = sv.w;
    } else {
        for (int i = i4; i < min(i4 + 4, E); i++) {
            int sIdx, d;
            if (g_is64) {
                const long long* p = (const long long*)ei;
                sIdx = (int)p[i]; d = (int)p[i + E];
            } else {
                const int* p = (const int*)ei;
                sIdx = p[i]; d = p[i + E];
            }
            g_csr[atomicAdd(&g_cursor[d], 1)] = sIdx;
        }
    }
}

// ---------------- split-tf32 tensor-core GEMM (software pipelined) ----------------
__device__ __forceinline__ void cvt_split(float x, unsigned& hi, unsigned& lo) {
    asm("cvt.rna.tf32.f32 %0, %1;" : "=r"(hi) : "f"(x));
    float l = x - __uint_as_float(hi);
    asm("cvt.rna.tf32.f32 %0, %1;" : "=r"(lo) : "f"(l));
}

__device__ __forceinline__ void mma8(float* c, const unsigned* a, const unsigned* b) {
    asm volatile(
        "mma.sync.aligned.m16n8k8.row.col.f32.tf32.tf32.f32 "
        "{%0,%1,%2,%3},{%4,%5,%6,%7},{%8,%9},{%0,%1,%2,%3};"
        : "+f"(c[0]), "+f"(c[1]), "+f"(c[2]), "+f"(c[3])
        : "r"(a[0]), "r"(a[1]), "r"(a[2]), "r"(a[3]), "r"(b[0]), "r"(b[1]));
}

// out[row,col] = (SCALE ? dis[row] : 1) * (A[row,:] @ W[:,col]), stored as f16.
// AHALF: A is f16 (exact in tf32 -> no A-lo correction, 2 MMAs instead of 3).
// rowOff: block row offset (for split-half launches).
// Pipelined: next tile prefetched to registers while MMAs consume current smem tile.
template<int BN, bool SCALE, bool AHALF>
__global__ void __launch_bounds__(256)
gemm_tf32(const void* __restrict__ Av, const float* __restrict__ W,
          __half* __restrict__ out, int M, int K, int rowOff)
{
    constexpr int BM = 128, BK = 16;
    constexpr int LDA = BK + 4;
    constexpr int LDB = BN + 8;
    constexpr int NF  = BN / 16;
    constexpr int F4PR = BN / 4;
    constexpr int B_ITERS = (BK * F4PR) / 256;

    __shared__ unsigned As_hi[BM * LDA];
    __shared__ unsigned As_lo[AHALF ? 1 : BM * LDA];
    __shared__ unsigned Bs_hi[BK * LDB], Bs_lo[BK * LDB];

    const int tid  = threadIdx.x;
    const int lane = tid & 31, warp = tid >> 5;
    const int wm = warp & 3, wn = warp >> 2;   // 4 x 2 warp grid
    const int row0 = blockIdx.x * BM + rowOff;

    float acc[2][NF][4] = {};

    // register staging
    uint4  ra_h;
    float4 ra_f0, ra_f1;
    float4 rb[B_ITERS];

    auto loadTiles = [&](int kk) {
        if (AHALF) {
            const __half* A = (const __half*)Av;
            int r = tid >> 1, c = (tid & 1) * 8;
            ra_h = make_uint4(0, 0, 0, 0);
            if (row0 + r < M)
                ra_h = *reinterpret_cast<const uint4*>(A + (size_t)(row0 + r) * K + kk + c);
        } else {
            const float* A = (const float*)Av;
            int r = tid >> 2, c = (tid & 3) * 4;
            ra_f0 = make_float4(0.f, 0.f, 0.f, 0.f);
            ra_f1 = make_float4(0.f, 0.f, 0.f, 0.f);
            if (row0 + r < M)
                ra_f0 = *reinterpret_cast<const float4*>(A + (size_t)(row0 + r) * K + kk + c);
            if (row0 + r + 64 < M)
                ra_f1 = *reinterpret_cast<const float4*>(A + (size_t)(row0 + r + 64) * K + kk + c);
        }
#pragma unroll
        for (int i = 0; i < B_ITERS; i++) {
            int flat = tid + i * 256;
            int r = flat / F4PR, c = (flat % F4PR) * 4;
            rb[i] = *reinterpret_cast<const float4*>(W + (size_t)(kk + r) * BN + c);
        }
    };

    auto storeTiles = [&]() {
        if (AHALF) {
            int r = tid >> 1, c = (tid & 1) * 8;
            const __half2* hp = reinterpret_cast<const __half2*>(&ra_h);
#pragma unroll
            for (int j = 0; j < 4; j++) {
                float2 f = __half22float2(hp[j]);
                As_hi[r*LDA + c + 2*j    ] = __float_as_uint(f.x);  // exact tf32
                As_hi[r*LDA + c + 2*j + 1] = __float_as_uint(f.y);
            }
        } else {
            int r = tid >> 2, c = (tid & 3) * 4;
            unsigned h, l;
            cvt_split(ra_f0.x, h, l); As_hi[r*LDA + c    ] = h; As_lo[r*LDA + c    ] = l;
            cvt_split(ra_f0.y, h, l); As_hi[r*LDA + c + 1] = h; As_lo[r*LDA + c + 1] = l;
            cvt_split(ra_f0.z, h, l); As_hi[r*LDA + c + 2] = h; As_lo[r*LDA + c + 2] = l;
            cvt_split(ra_f0.w, h, l); As_hi[r*LDA + c + 3] = h; As_lo[r*LDA + c + 3] = l;
            int r1 = r + 64;
            cvt_split(ra_f1.x, h, l); As_hi[r1*LDA + c    ] = h; As_lo[r1*LDA + c    ] = l;
            cvt_split(ra_f1.y, h, l); As_hi[r1*LDA + c + 1] = h; As_lo[r1*LDA + c + 1] = l;
            cvt_split(ra_f1.z, h, l); As_hi[r1*LDA + c + 2] = h; As_lo[r1*LDA + c + 2] = l;
            cvt_split(ra_f1.w, h, l); As_hi[r1*LDA + c + 3] = h; As_lo[r1*LDA + c + 3] = l;
        }
#pragma unroll
        for (int i = 0; i < B_ITERS; i++) {
            int flat = tid + i * 256;
            int r = flat / F4PR, c = (flat % F4PR) * 4;
            unsigned h, l;
            cvt_split(rb[i].x, h, l); Bs_hi[r*LDB + c    ] = h; Bs_lo[r*LDB + c    ] = l;
            cvt_split(rb[i].y, h, l); Bs_hi[r*LDB + c + 1] = h; Bs_lo[r*LDB + c + 1] = l;
            cvt_split(rb[i].z, h, l); Bs_hi[r*LDB + c + 2] = h; Bs_lo[r*LDB + c + 2] = l;
            cvt_split(rb[i].w, h, l); Bs_hi[r*LDB + c + 3] = h; Bs_lo[r*LDB + c + 3] = l;
        }
    };

    auto compute = [&]() {
#pragma unroll
        for (int ks = 0; ks < 2; ks++) {
            const int k0 = ks * 8;
            unsigned ah[2][4], al[2][4];
#pragma unroll
            for (int mf = 0; mf < 2; mf++) {
                int r = wm * 32 + mf * 16 + (lane >> 2);
                int c = k0 + (lane & 3);
                ah[mf][0] = As_hi[ r      * LDA + c    ];
                ah[mf][1] = As_hi[(r + 8) * LDA + c    ];
                ah[mf][2] = As_hi[ r      * LDA + c + 4];
                ah[mf][3] = As_hi[(r + 8) * LDA + c + 4];
                if (!AHALF) {
                    al[mf][0] = As_lo[ r      * LDA + c    ];
                    al[mf][1] = As_lo[(r + 8) * LDA + c    ];
                    al[mf][2] = As_lo[ r      * LDA + c + 4];
                    al[mf][3] = As_lo[(r + 8) * LDA + c + 4];
                }
            }
#pragma unroll
            for (int nf = 0; nf < NF; nf++) {
                int n = wn * (BN / 2) + nf * 8 + (lane >> 2);
                int kb = k0 + (lane & 3);
                unsigned bh[2], bl[2];
                bh[0] = Bs_hi[ kb      * LDB + n];
                bh[1] = Bs_hi[(kb + 4) * LDB + n];
                bl[0] = Bs_lo[ kb      * LDB + n];
                bl[1] = Bs_lo[(kb + 4) * LDB + n];
#pragma unroll
                for (int mf = 0; mf < 2; mf++) {
                    mma8(acc[mf][nf], ah[mf], bh);
                    mma8(acc[mf][nf], ah[mf], bl);
                    if (!AHALF) mma8(acc[mf][nf], al[mf], bh);
                }
            }
        }
    };

    // pipelined mainloop: prefetch next tile while computing current
    loadTiles(0);
    storeTiles();
    __syncthreads();
    for (int kk = BK; kk < K; kk += BK) {
        loadTiles(kk);     // global loads in flight during compute
        compute();
        __syncthreads();
        storeTiles();
        __syncthreads();
    }
    compute();

    // epilogue
#pragma unroll
    for (int mf = 0; mf < 2; mf++) {
        int r0 = row0 + wm * 32 + mf * 16 + (lane >> 2);
        int r1 = r0 + 8;
        float d0 = 1.f, d1 = 1.f;
        if (SCALE) {
            d0 = (r0 < M) ? g_dis[r0] : 0.f;
            d1 = (r1 < M) ? g_dis[r1] : 0.f;
        }
#pragma unroll
        for (int nf = 0; nf < NF; nf++) {
            int c = wn * (BN / 2) + nf * 8 + (lane & 3) * 2;
            if (r0 < M)
                *reinterpret_cast<__half2*>(out + (size_t)r0 * BN + c) =
                    __floats2half2_rn(acc[mf][nf][0] * d0, acc[mf][nf][1] * d0);
            if (r1 < M)
                *reinterpret_cast<__half2*>(out + (size_t)r1 * BN + c) =
                    __floats2half2_rn(acc[mf][nf][2] * d1, acc[mf][nf][3] * d1);
        }
    }
}

// ---------------- gather aggregation (f16 rows, f32 accumulate) ----------------
__device__ __forceinline__ void acch(float* a, uint2 v, float s) {
    __half2 h0 = *reinterpret_cast<__half2*>(&v.x);
    __half2 h1 = *reinterpret_cast<__half2*>(&v.y);
    float2 f0 = __half22float2(h0), f1 = __half22float2(h1);
    a[0] = fmaf(s, f0.x, a[0]);
    a[1] = fmaf(s, f0.y, a[1]);
    a[2] = fmaf(s, f1.x, a[2]);
    a[3] = fmaf(s, f1.y, a[3]);
}

__device__ __forceinline__ void acch2(float* a, unsigned v, float s) {
    float2 f = __half22float2(*reinterpret_cast<__half2*>(&v));
    a[0] = fmaf(s, f.x, a[0]);
    a[1] = fmaf(s, f.y, a[1]);
}

// layer 1, node range [nodeBeg, nodeEnd): one warp per node, 8B per lane
__global__ void k_agg128(const __half* __restrict__ hs, __half* __restrict__ out,
                         const float* __restrict__ bias, int nodeBeg, int nodeEnd)
{
    int w = nodeBeg + ((blockIdx.x * blockDim.x + threadIdx.x) >> 5);
    if (w >= nodeEnd) return;
    int lane = threadIdx.x & 31;
    const uint2* base = (const uint2*)hs;   // 32 uint2 per row

    int beg = g_start[w], cnt = g_cnt[w];
    float dw = g_dis[w];
    float a[4] = {0.f, 0.f, 0.f, 0.f};
    acch(a, base[(size_t)w * 32 + lane], dw);   // self loop

    int e = 0;
    for (; e + 8 <= cnt; e += 8) {
        int s0 = g_csr[beg+e  ], s1 = g_csr[beg+e+1], s2 = g_csr[beg+e+2], s3 = g_csr[beg+e+3];
        int s4 = g_csr[beg+e+4], s5 = g_csr[beg+e+5], s6 = g_csr[beg+e+6], s7 = g_csr[beg+e+7];
        uint2 v0 = base[(size_t)s0*32+lane], v1 = base[(size_t)s1*32+lane];
        uint2 v2 = base[(size_t)s2*32+lane], v3 = base[(size_t)s3*32+lane];
        uint2 v4 = base[(size_t)s4*32+lane], v5 = base[(size_t)s5*32+lane];
        uint2 v6 = base[(size_t)s6*32+lane], v7 = base[(size_t)s7*32+lane];
        acch(a, v0, g_dis[s0]); acch(a, v1, g_dis[s1]);
        acch(a, v2, g_dis[s2]); acch(a, v3, g_dis[s3]);
        acch(a, v4, g_dis[s4]); acch(a, v5, g_dis[s5]);
        acch(a, v6, g_dis[s6]); acch(a, v7, g_dis[s7]);
    }
    for (; e < cnt; e++) {
        int s = g_csr[beg + e];
        acch(a, base[(size_t)s*32+lane], g_dis[s]);
    }

    float4 b = ((const float4*)bias)[lane];
    uint2 r;
    __half2 r0 = __floats2half2_rn(fmaxf(fmaf(dw, a[0], b.x), 0.f),
                                   fmaxf(fmaf(dw, a[1], b.y), 0.f));
    __half2 r1 = __floats2half2_rn(fmaxf(fmaf(dw, a[2], b.z), 0.f),
                                   fmaxf(fmaf(dw, a[3], b.w), 0.f));
    r.x = *reinterpret_cast<unsigned*>(&r0);
    r.y = *reinterpret_cast<unsigned*>(&r1);
    ((uint2*)out)[(size_t)w * 32 + lane] = r;
}

// layer 2: one warp per node, 4B (half2) per lane
__global__ void k_agg64(const __half* __restrict__ hs, float* __restrict__ out,
                        const float* __restrict__ bias, int N)
{
    int node = (blockIdx.x * blockDim.x + threadIdx.x) >> 5;
    if (node >= N) return;
    int lane = threadIdx.x & 31;
    const unsigned* base = (const unsigned*)hs;   // 32 half2 per row

    int beg = g_start[node], cnt = g_cnt[node];
    float a[2] = {0.f, 0.f};
    acch2(a, base[(size_t)node * 32 + lane], 1.f);   // self loop (already scaled)

    int e = 0;
    for (; e + 8 <= cnt; e += 8) {
        int s0 = g_csr[beg+e  ], s1 = g_csr[beg+e+1], s2 = g_csr[beg+e+2], s3 = g_csr[beg+e+3];
        int s4 = g_csr[beg+e+4], s5 = g_csr[beg+e+5], s6 = g_csr[beg+e+6], s7 = g_csr[beg+e+7];
        unsigned v0 = base[(size_t)s0*32+lane], v1 = base[(size_t)s1*32+lane];
        unsigned v2 = base[(size_t)s2*32+lane], v3 = base[(size_t)s3*32+lane];
        unsigned v4 = base[(size_t)s4*32+lane], v5 = base[(size_t)s5*32+lane];
        unsigned v6 = base[(size_t)s6*32+lane], v7 = base[(size_t)s7*32+lane];
        acch2(a, v0, 1.f); acch2(a, v1, 1.f); acch2(a, v2, 1.f); acch2(a, v3, 1.f);
        acch2(a, v4, 1.f); acch2(a, v5, 1.f); acch2(a, v6, 1.f); acch2(a, v7, 1.f);
    }
    for (; e < cnt; e++)
        acch2(a, base[(size_t)g_csr[beg+e]*32+lane], 1.f);

    float dw = g_dis[node];
    float2 b = ((const float2*)bias)[lane];
    float2 r;
    r.x = fmaf(dw, a[0], b.x);
    r.y = fmaf(dw, a[1], b.y);
    ((float2*)out)[(size_t)node * 32 + lane] = r;
}

// ---------------- launch ----------------
extern "C" void kernel_launch(void* const* d_in, const int* in_sizes, int n_in,
                              void* d_out, int out_size)
{
    const float* x   = (const float*)d_in[0];
    const void*  ei  = d_in[1];
    const float* W1  = (const float*)d_in[2];
    const float* b1  = (const float*)d_in[3];
    const float* W2  = (const float*)d_in[4];
    const float* b2  = (const float*)d_in[5];
    float*       out = (float*)d_out;

    const int N = in_sizes[0] / IN_C;   // 50000
    const int E = in_sizes[1] / 2;      // 800000
    const int nscan = (N + SCAN_B - 1) / SCAN_B;
    const int e4blocks = ((E + 3) / 4 + 255) / 256;

    __half *p_hs1, *p_act1, *p_hs2;
    cudaGetSymbolAddress((void**)&p_hs1,  g_hs1);
    cudaGetSymbolAddress((void**)&p_act1, g_act1);
    cudaGetSymbolAddress((void**)&p_hs2,  g_hs2);

    // one-time side stream + events
    static cudaStream_t s2 = nullptr;
    static cudaEvent_t evFork = nullptr, evJoin = nullptr, evA0 = nullptr, evG0 = nullptr;
    if (!s2) {
        if (cudaStreamCreateWithFlags(&s2, cudaStreamNonBlocking) != cudaSuccess) s2 = nullptr;
        if (s2) {
            cudaEventCreateWithFlags(&evFork, cudaEventDisableTiming);
            cudaEventCreateWithFlags(&evJoin, cudaEventDisableTiming);
            cudaEventCreateWithFlags(&evA0,   cudaEventDisableTiming);
            cudaEventCreateWithFlags(&evG0,   cudaEventDisableTiming);
        }
    }

    // ---- fork: GEMM1 on side stream, overlapping CSR build ----
    bool forked = false;
    if (s2) {
        cudaEventRecord(evFork, 0);
        cudaStreamWaitEvent(s2, evFork, 0);
        gemm_tf32<HID, false, false><<<(N + 127) / 128, 256, 0, s2>>>(x, W1, p_hs1, N, IN_C, 0);
        cudaEventRecord(evJoin, s2);
        forked = true;
    }

    // ---- main stream: CSR build + dis ----
    k_zero_detect<<<(N + 255) / 256, 256>>>((const long long*)ei, N);
    k_hist<<<e4blocks, 256>>>(ei, E);
    k_scan1<<<nscan, SCAN_B>>>(N);
    k_scan3<<<nscan, SCAN_B>>>(N, nscan);
    k_fill<<<e4blocks, 256>>>(ei, E);

    if (forked) cudaStreamWaitEvent(0, evJoin, 0);
    else        gemm_tf32<HID, false, false><<<(N + 127) / 128, 256>>>(x, W1, p_hs1, N, IN_C, 0);

    if (forked) {
        // ---- layer 1 agg (half0) -> GEMM2(half0) on side stream, overlapped
        //      with layer 1 agg (half1) + GEMM2(half1) on main ----
        const int H0 = ((N / 2 + 127) / 128) * 128;   // 25088, block-aligned
        k_agg128<<<(H0 * 32 + 255) / 256, 256>>>(p_hs1, p_act1, b1, 0, H0);
        cudaEventRecord(evA0, 0);
        cudaStreamWaitEvent(s2, evA0, 0);
        gemm_tf32<OUTC, true, true><<<H0 / 128, 256, 0, s2>>>(p_act1, W2, p_hs2, N, HID, 0);
        cudaEventRecord(evG0, s2);

        k_agg128<<<((N - H0) * 32 + 255) / 256, 256>>>(p_hs1, p_act1, b1, H0, N);
        gemm_tf32<OUTC, true, true><<<(N - H0 + 127) / 128, 256>>>(p_act1, W2, p_hs2, N, HID, H0);
        cudaStreamWaitEvent(0, evG0, 0);
    } else {
        k_agg128<<<(N * 32 + 255) / 256, 256>>>(p_hs1, p_act1, b1, 0, N);
        gemm_tf32<OUTC, true, true><<<(N + 127) / 128, 256>>>(p_act1, W2, p_hs2, N, HID, 0);
    }

    // ---- layer 2 aggregate -> d_out ----
    k_agg64<<<(N * 32 + 255) / 256, 256>>>(p_hs2, out, b2, N);
}

// round 11
// speedup vs baseline: 1.3704x; 1.3681x over previous
#include <cuda_runtime.h>
#include <cuda_fp16.h>
#include <cuda_bf16.h>
#include <cstdint>

#define MAX_N 50000
#define MAX_E 800000
#define IN_C  256
#define HID   128
#define OUTC  64
#define SCAN_B 256
#define SCAN_NBLK ((MAX_N + SCAN_B - 1) / SCAN_B)   // 196

// ---- scratch (device globals: no allocations allowed) ----
__device__ int    g_is64;
__device__ int    g_csr[MAX_E];
__device__ int    g_cnt[MAX_N];
__device__ int    g_start[MAX_N];
__device__ int    g_cursor[MAX_N];
__device__ int    g_bsum[SCAN_NBLK];
__device__ float  g_dis[MAX_N];
__device__ __half g_hs1[MAX_N * HID];   // UNSCALED layer-1 GEMM output (f16)
__device__ __half g_act1[MAX_N * HID];  // relu'd layer-1 output (f16)
__device__ __half g_hs2[MAX_N * OUTC];  // dis-scaled layer-2 GEMM output (f16)

// ---------------- CSR build ----------------
__global__ void k_zero_detect(const long long* __restrict__ ei, int n) {
    int i = blockIdx.x * blockDim.x + threadIdx.x;
    if (i < n) g_cnt[i] = 0;
    if (blockIdx.x == 0) {
        __shared__ int ok;
        if (threadIdx.x == 0) ok = 1;
        __syncthreads();
        long long v = ei[threadIdx.x];
        if (v < 0 || v >= MAX_N) ok = 0;
        __syncthreads();
        if (threadIdx.x == 0) g_is64 = ok;
    }
}

__global__ void k_hist(const void* __restrict__ ei, int E) {
    int i4 = (blockIdx.x * blockDim.x + threadIdx.x) * 4;
    if (i4 >= E) return;
    if (!g_is64 && i4 + 4 <= E) {
        int4 d = *reinterpret_cast<const int4*>((const int*)ei + E + i4);
        atomicAdd(&g_cnt[d.x], 1);
        atomicAdd(&g_cnt[d.y], 1);
        atomicAdd(&g_cnt[d.z], 1);
        atomicAdd(&g_cnt[d.w], 1);
    } else {
        for (int i = i4; i < min(i4 + 4, E); i++) {
            int d = g_is64 ? (int)((const long long*)ei)[i + E]
                           : ((const int*)ei)[i + E];
            atomicAdd(&g_cnt[d], 1);
        }
    }
}

__global__ void k_scan1(int n) {
    __shared__ int s[SCAN_B];
    int i = blockIdx.x * SCAN_B + threadIdx.x;
    int v = (i < n) ? g_cnt[i] : 0;
    s[threadIdx.x] = v;
    __syncthreads();
#pragma unroll
    for (int off = 1; off < SCAN_B; off <<= 1) {
        int x = (threadIdx.x >= off) ? s[threadIdx.x - off] : 0;
        __syncthreads();
        s[threadIdx.x] += x;
        __syncthreads();
    }
    if (i < n) g_start[i] = s[threadIdx.x] - v;
    if (threadIdx.x == SCAN_B - 1) g_bsum[blockIdx.x] = s[SCAN_B - 1];
}

__global__ void k_scan3(int n, int nblk) {
    __shared__ int s[SCAN_B];
    int v = (threadIdx.x < nblk) ? g_bsum[threadIdx.x] : 0;
    s[threadIdx.x] = v;
    __syncthreads();
#pragma unroll
    for (int off = 1; off < SCAN_B; off <<= 1) {
        int x = (threadIdx.x >= off) ? s[threadIdx.x - off] : 0;
        __syncthreads();
        s[threadIdx.x] += x;
        __syncthreads();
    }
    int boff = (blockIdx.x == 0) ? 0 : s[blockIdx.x - 1];
    int i = blockIdx.x * SCAN_B + threadIdx.x;
    if (i >= n) return;
    int st = g_start[i] + boff;
    g_start[i]  = st;
    g_cursor[i] = st;
    g_dis[i]    = rsqrtf((float)(g_cnt[i] + 1));
}

__global__ void k_fill(const void* __restrict__ ei, int E) {
    int i4 = (blockIdx.x * blockDim.x + threadIdx.x) * 4;
    if (i4 >= E) return;
    if (!g_is64 && i4 + 4 <= E) {
        int4 sv = *reinterpret_cast<const int4*>((const int*)ei + i4);
        int4 dv = *reinterpret_cast<const int4*>((const int*)ei + E + i4);
        g_csr[atomicAdd(&g_cursor[dv.x], 1)] = sv.x;
        g_csr[atomicAdd(&g_cursor[dv.y], 1)] = sv.y;
        g_csr[atomicAdd(&g_cursor[dv.z], 1)] = sv.z;
        g_csr[atomicAdd(&g_cursor[dv.w], 1)] = sv.w;
    } else {
        for (int i = i4; i < min(i4 + 4, E); i++) {
            int sIdx, d;
            if (g_is64) {
                const long long* p = (const long long*)ei;
                sIdx = (int)p[i]; d = (int)p[i + E];
            } else {
                const int* p = (const int*)ei;
                sIdx = p[i]; d = p[i + E];
            }
            g_csr[atomicAdd(&g_cursor[d], 1)] = sIdx;
        }
    }
}

// ---------------- 16-bit k16 tensor-core GEMM ----------------
// GEMM1 (FP16A=false): split-bf16 3-MMA  (hi*hi + hi*lo + lo*hi), A f32, W f32.
// GEMM2 (FP16A=true):  f16 2-MMA (A exact f16; W split into f16 hi+lo).

__device__ __forceinline__ void mma16b(float* c, const unsigned* a, const unsigned* b) {
    asm volatile(
        "mma.sync.aligned.m16n8k16.row.col.f32.bf16.bf16.f32 "
        "{%0,%1,%2,%3},{%4,%5,%6,%7},{%8,%9},{%0,%1,%2,%3};"
        : "+f"(c[0]), "+f"(c[1]), "+f"(c[2]), "+f"(c[3])
        : "r"(a[0]), "r"(a[1]), "r"(a[2]), "r"(a[3]), "r"(b[0]), "r"(b[1]));
}

__device__ __forceinline__ void mma16h(float* c, const unsigned* a, const unsigned* b) {
    asm volatile(
        "mma.sync.aligned.m16n8k16.row.col.f32.f16.f16.f32 "
        "{%0,%1,%2,%3},{%4,%5,%6,%7},{%8,%9},{%0,%1,%2,%3};"
        : "+f"(c[0]), "+f"(c[1]), "+f"(c[2]), "+f"(c[3])
        : "r"(a[0]), "r"(a[1]), "r"(a[2]), "r"(a[3]), "r"(b[0]), "r"(b[1]));
}

// split f32 pair (even,odd k) into packed bf16 hi + bf16 lo
__device__ __forceinline__ void split2_bf16(float e, float o, unsigned& hi, unsigned& lo) {
    __nv_bfloat16 he = __float2bfloat16_rn(e), ho = __float2bfloat16_rn(o);
    float re = e - __bfloat162float(he), ro = o - __bfloat162float(ho);
    __nv_bfloat162 h; h.x = he; h.y = ho;
    __nv_bfloat162 l = __floats2bfloat162_rn(re, ro);
    hi = *reinterpret_cast<unsigned*>(&h);
    lo = *reinterpret_cast<unsigned*>(&l);
}

// split f32 pair into packed f16 hi + f16 lo
__device__ __forceinline__ void split2_f16(float e, float o, unsigned& hi, unsigned& lo) {
    __half he = __float2half_rn(e), ho = __float2half_rn(o);
    float re = e - __half2float(he), ro = o - __half2float(ho);
    __half2 h; h.x = he; h.y = ho;
    __half2 l = __floats2half2_rn(re, ro);
    hi = *reinterpret_cast<unsigned*>(&h);
    lo = *reinterpret_cast<unsigned*>(&l);
}

template<int BN, bool SCALE, bool FP16A>
__global__ void __launch_bounds__(256)
gemm16(const void* __restrict__ Av, const float* __restrict__ W,
       __half* __restrict__ out, int M, int K)
{
    constexpr int BM = 128, BK = 16;
    constexpr int LDP = 12;              // pairs per row + pad (8 data + 4); 12r mod 32 spans all bank groups
    constexpr int NF  = BN / 16;
    constexpr int B_PITER = BN / 32;     // pair-staging iters (8*BN/256)

    __shared__ unsigned As_hi[BM * LDP];
    __shared__ unsigned As_lo[FP16A ? 1 : BM * LDP];
    __shared__ unsigned Bs_hi[BN * LDP], Bs_lo[BN * LDP];

    const int tid  = threadIdx.x;
    const int lane = tid & 31, warp = tid >> 5;
    const int wm = warp & 3, wn = warp >> 2;   // 4 x 2 warp grid
    const int row0 = blockIdx.x * BM;

    float acc[2][NF][4] = {};

    // register staging
    uint4  ra_h;                 // FP16A: 8 halves (4 packed pairs)
    float4 ra_f0, ra_f1;         // !FP16A: 4 floats x 2 row segments
    float  rbe[B_PITER], rbo[B_PITER];   // B even/odd-k floats

    auto loadTiles = [&](int kk) {
        if (FP16A) {
            const __half* A = (const __half*)Av;
            int r = tid >> 1, c = (tid & 1) * 8;
            ra_h = make_uint4(0, 0, 0, 0);
            if (row0 + r < M)
                ra_h = *reinterpret_cast<const uint4*>(A + (size_t)(row0 + r) * K + kk + c);
        } else {
            const float* A = (const float*)Av;
            int r = tid >> 2, c = (tid & 3) * 4;
            ra_f0 = make_float4(0.f, 0.f, 0.f, 0.f);
            ra_f1 = make_float4(0.f, 0.f, 0.f, 0.f);
            if (row0 + r < M)
                ra_f0 = *reinterpret_cast<const float4*>(A + (size_t)(row0 + r) * K + kk + c);
            if (row0 + r + 64 < M)
                ra_f1 = *reinterpret_cast<const float4*>(A + (size_t)(row0 + r + 64) * K + kk + c);
        }
#pragma unroll
        for (int i = 0; i < B_PITER; i++) {
            int idx = tid + i * 256;
            int kp = idx / BN, n = idx % BN;
            rbe[i] = W[(size_t)(kk + 2 * kp    ) * BN + n];
            rbo[i] = W[(size_t)(kk + 2 * kp + 1) * BN + n];
        }
    };

    auto storeTiles = [&]() {
        if (FP16A) {
            int r = tid >> 1, p0 = (tid & 1) * 4;
            As_hi[r*LDP + p0    ] = ra_h.x;   // already packed f16 pairs (exact)
            As_hi[r*LDP + p0 + 1] = ra_h.y;
            As_hi[r*LDP + p0 + 2] = ra_h.z;
            As_hi[r*LDP + p0 + 3] = ra_h.w;
        } else {
            int r = tid >> 2, p0 = (tid & 3) * 2;
            unsigned h, l;
            split2_bf16(ra_f0.x, ra_f0.y, h, l); As_hi[r*LDP + p0    ] = h; As_lo[r*LDP + p0    ] = l;
            split2_bf16(ra_f0.z, ra_f0.w, h, l); As_hi[r*LDP + p0 + 1] = h; As_lo[r*LDP + p0 + 1] = l;
            int r1 = r + 64;
            split2_bf16(ra_f1.x, ra_f1.y, h, l); As_hi[r1*LDP + p0    ] = h; As_lo[r1*LDP + p0    ] = l;
            split2_bf16(ra_f1.z, ra_f1.w, h, l); As_hi[r1*LDP + p0 + 1] = h; As_lo[r1*LDP + p0 + 1] = l;
        }
#pragma unroll
        for (int i = 0; i < B_PITER; i++) {
            int idx = tid + i * 256;
            int kp = idx / BN, n = idx % BN;
            unsigned h, l;
            if (FP16A) split2_f16 (rbe[i], rbo[i], h, l);
            else       split2_bf16(rbe[i], rbo[i], h, l);
            Bs_hi[n*LDP + kp] = h;
            Bs_lo[n*LDP + kp] = l;
        }
    };

    auto compute = [&]() {
        unsigned ah[2][4], al[2][4];
        const int q = lane & 3;
#pragma unroll
        for (int mf = 0; mf < 2; mf++) {
            int r = wm * 32 + mf * 16 + (lane >> 2);
            ah[mf][0] = As_hi[ r      * LDP + q    ];
            ah[mf][1] = As_hi[(r + 8) * LDP + q    ];
            ah[mf][2] = As_hi[ r      * LDP + q + 4];
            ah[mf][3] = As_hi[(r + 8) * LDP + q + 4];
            if (!FP16A) {
                al[mf][0] = As_lo[ r      * LDP + q    ];
                al[mf][1] = As_lo[(r + 8) * LDP + q    ];
                al[mf][2] = As_lo[ r      * LDP + q + 4];
                al[mf][3] = As_lo[(r + 8) * LDP + q + 4];
            }
        }
#pragma unroll
        for (int nf = 0; nf < NF; nf++) {
            int n = wn * (BN / 2) + nf * 8 + (lane >> 2);
            unsigned bh[2], bl[2];
            bh[0] = Bs_hi[n*LDP + q];
            bh[1] = Bs_hi[n*LDP + q + 4];
            bl[0] = Bs_lo[n*LDP + q];
            bl[1] = Bs_lo[n*LDP + q + 4];
#pragma unroll
            for (int mf = 0; mf < 2; mf++) {
                if (FP16A) {
                    mma16h(acc[mf][nf], ah[mf], bh);
                    mma16h(acc[mf][nf], ah[mf], bl);
                } else {
                    mma16b(acc[mf][nf], ah[mf], bh);
                    mma16b(acc[mf][nf], ah[mf], bl);
                    mma16b(acc[mf][nf], al[mf], bh);
                }
            }
        }
    };

    // pipelined mainloop
    loadTiles(0);
    storeTiles();
    __syncthreads();
    for (int kk = BK; kk < K; kk += BK) {
        loadTiles(kk);
        compute();
        __syncthreads();
        storeTiles();
        __syncthreads();
    }
    compute();

    // epilogue
#pragma unroll
    for (int mf = 0; mf < 2; mf++) {
        int r0 = row0 + wm * 32 + mf * 16 + (lane >> 2);
        int r1 = r0 + 8;
        float d0 = 1.f, d1 = 1.f;
        if (SCALE) {
            d0 = (r0 < M) ? g_dis[r0] : 0.f;
            d1 = (r1 < M) ? g_dis[r1] : 0.f;
        }
#pragma unroll
        for (int nf = 0; nf < NF; nf++) {
            int c = wn * (BN / 2) + nf * 8 + (lane & 3) * 2;
            if (r0 < M)
                *reinterpret_cast<__half2*>(out + (size_t)r0 * BN + c) =
                    __floats2half2_rn(acc[mf][nf][0] * d0, acc[mf][nf][1] * d0);
            if (r1 < M)
                *reinterpret_cast<__half2*>(out + (size_t)r1 * BN + c) =
                    __floats2half2_rn(acc[mf][nf][2] * d1, acc[mf][nf][3] * d1);
        }
    }
}

// ---------------- gather aggregation (f16 rows, f32 accumulate) ----------------
__device__ __forceinline__ void acch(float* a, uint2 v, float s) {
    __half2 h0 = *reinterpret_cast<__half2*>(&v.x);
    __half2 h1 = *reinterpret_cast<__half2*>(&v.y);
    float2 f0 = __half22float2(h0), f1 = __half22float2(h1);
    a[0] = fmaf(s, f0.x, a[0]);
    a[1] = fmaf(s, f0.y, a[1]);
    a[2] = fmaf(s, f1.x, a[2]);
    a[3] = fmaf(s, f1.y, a[3]);
}

__device__ __forceinline__ void acch2(float* a, unsigned v, float s) {
    float2 f = __half22float2(*reinterpret_cast<__half2*>(&v));
    a[0] = fmaf(s, f.x, a[0]);
    a[1] = fmaf(s, f.y, a[1]);
}

// layer 1: one warp per node, 8B per lane
__global__ void k_agg128(const __half* __restrict__ hs, __half* __restrict__ out,
                         const float* __restrict__ bias, int N)
{
    int w = (blockIdx.x * blockDim.x + threadIdx.x) >> 5;
    if (w >= N) return;
    int lane = threadIdx.x & 31;
    const uint2* base = (const uint2*)hs;

    int beg = g_start[w], cnt = g_cnt[w];
    float dw = g_dis[w];
    float a[4] = {0.f, 0.f, 0.f, 0.f};
    acch(a, base[(size_t)w * 32 + lane], dw);   // self loop

    int e = 0;
    for (; e + 8 <= cnt; e += 8) {
        int s0 = g_csr[beg+e  ], s1 = g_csr[beg+e+1], s2 = g_csr[beg+e+2], s3 = g_csr[beg+e+3];
        int s4 = g_csr[beg+e+4], s5 = g_csr[beg+e+5], s6 = g_csr[beg+e+6], s7 = g_csr[beg+e+7];
        uint2 v0 = base[(size_t)s0*32+lane], v1 = base[(size_t)s1*32+lane];
        uint2 v2 = base[(size_t)s2*32+lane], v3 = base[(size_t)s3*32+lane];
        uint2 v4 = base[(size_t)s4*32+lane], v5 = base[(size_t)s5*32+lane];
        uint2 v6 = base[(size_t)s6*32+lane], v7 = base[(size_t)s7*32+lane];
        acch(a, v0, g_dis[s0]); acch(a, v1, g_dis[s1]);
        acch(a, v2, g_dis[s2]); acch(a, v3, g_dis[s3]);
        acch(a, v4, g_dis[s4]); acch(a, v5, g_dis[s5]);
        acch(a, v6, g_dis[s6]); acch(a, v7, g_dis[s7]);
    }
    for (; e < cnt; e++) {
        int s = g_csr[beg + e];
        acch(a, base[(size_t)s*32+lane], g_dis[s]);
    }

    float4 b = ((const float4*)bias)[lane];
    uint2 r;
    __half2 r0 = __floats2half2_rn(fmaxf(fmaf(dw, a[0], b.x), 0.f),
                                   fmaxf(fmaf(dw, a[1], b.y), 0.f));
    __half2 r1 = __floats2half2_rn(fmaxf(fmaf(dw, a[2], b.z), 0.f),
                                   fmaxf(fmaf(dw, a[3], b.w), 0.f));
    r.x = *reinterpret_cast<unsigned*>(&r0);
    r.y = *reinterpret_cast<unsigned*>(&r1);
    ((uint2*)out)[(size_t)w * 32 + lane] = r;
}

// layer 2: one warp per node, 4B (half2) per lane
__global__ void k_agg64(const __half* __restrict__ hs, float* __restrict__ out,
                        const float* __restrict__ bias, int N)
{
    int node = (blockIdx.x * blockDim.x + threadIdx.x) >> 5;
    if (node >= N) return;
    int lane = threadIdx.x & 31;
    const unsigned* base = (const unsigned*)hs;

    int beg = g_start[node], cnt = g_cnt[node];
    float a[2] = {0.f, 0.f};
    acch2(a, base[(size_t)node * 32 + lane], 1.f);   // self loop (already scaled)

    int e = 0;
    for (; e + 8 <= cnt; e += 8) {
        int s0 = g_csr[beg+e  ], s1 = g_csr[beg+e+1], s2 = g_csr[beg+e+2], s3 = g_csr[beg+e+3];
        int s4 = g_csr[beg+e+4], s5 = g_csr[beg+e+5], s6 = g_csr[beg+e+6], s7 = g_csr[beg+e+7];
        unsigned v0 = base[(size_t)s0*32+lane], v1 = base[(size_t)s1*32+lane];
        unsigned v2 = base[(size_t)s2*32+lane], v3 = base[(size_t)s3*32+lane];
        unsigned v4 = base[(size_t)s4*32+lane], v5 = base[(size_t)s5*32+lane];
        unsigned v6 = base[(size_t)s6*32+lane], v7 = base[(size_t)s7*32+lane];
        acch2(a, v0, 1.f); acch2(a, v1, 1.f); acch2(a, v2, 1.f); acch2(a, v3, 1.f);
        acch2(a, v4, 1.f); acch2(a, v5, 1.f); acch2(a, v6, 1.f); acch2(a, v7, 1.f);
    }
    for (; e < cnt; e++)
        acch2(a, base[(size_t)g_csr[beg+e]*32+lane], 1.f);

    float dw = g_dis[node];
    float2 b = ((const float2*)bias)[lane];
    float2 r;
    r.x = fmaf(dw, a[0], b.x);
    r.y = fmaf(dw, a[1], b.y);
    ((float2*)out)[(size_t)node * 32 + lane] = r;
}

// ---------------- launch ----------------
extern "C" void kernel_launch(void* const* d_in, const int* in_sizes, int n_in,
                              void* d_out, int out_size)
{
    const float* x   = (const float*)d_in[0];
    const void*  ei  = d_in[1];
    const float* W1  = (const float*)d_in[2];
    const float* b1  = (const float*)d_in[3];
    const float* W2  = (const float*)d_in[4];
    const float* b2  = (const float*)d_in[5];
    float*       out = (float*)d_out;

    const int N = in_sizes[0] / IN_C;   // 50000
    const int E = in_sizes[1] / 2;      // 800000
    const int nscan = (N + SCAN_B - 1) / SCAN_B;
    const int e4blocks = ((E + 3) / 4 + 255) / 256;

    __half *p_hs1, *p_act1, *p_hs2;
    cudaGetSymbolAddress((void**)&p_hs1,  g_hs1);
    cudaGetSymbolAddress((void**)&p_act1, g_act1);
    cudaGetSymbolAddress((void**)&p_hs2,  g_hs2);

    static cudaStream_t s2 = nullptr;
    static cudaEvent_t evFork = nullptr, evJoin = nullptr;
    if (!s2) {
        if (cudaStreamCreateWithFlags(&s2, cudaStreamNonBlocking) != cudaSuccess) s2 = nullptr;
        if (s2) {
            cudaEventCreateWithFlags(&evFork, cudaEventDisableTiming);
            cudaEventCreateWithFlags(&evJoin, cudaEventDisableTiming);
        }
    }

    // ---- fork: GEMM1 (split-bf16) on side stream, overlapping CSR build ----
    bool forked = false;
    if (s2) {
        cudaEventRecord(evFork, 0);
        cudaStreamWaitEvent(s2, evFork, 0);
        gemm16<HID, false, false><<<(N + 127) / 128, 256, 0, s2>>>(x, W1, p_hs1, N, IN_C);
        cudaEventRecord(evJoin, s2);
        forked = true;
    }

    // ---- main stream: CSR build + dis ----
    k_zero_detect<<<(N + 255) / 256, 256>>>((const long long*)ei, N);
    k_hist<<<e4blocks, 256>>>(ei, E);
    k_scan1<<<nscan, SCAN_B>>>(N);
    k_scan3<<<nscan, SCAN_B>>>(N, nscan);
    k_fill<<<e4blocks, 256>>>(ei, E);

    if (forked) cudaStreamWaitEvent(0, evJoin, 0);
    else        gemm16<HID, false, false><<<(N + 127) / 128, 256>>>(x, W1, p_hs1, N, IN_C);

    // ---- layer 1 aggregate (+dis both sides, bias, relu) -> f16 act1 ----
    k_agg128<<<(N * 32 + 255) / 256, 256>>>(p_hs1, p_act1, b1, N);

    // ---- layer 2 GEMM (f16 A exact, W2 f16-split, dis-scaled) + aggregate ----
    gemm16<OUTC, true, true><<<(N + 127) / 128, 256>>>(p_act1, W2, p_hs2, N, HID);
    k_agg64<<<(N * 32 + 255) / 256, 256>>>(p_hs2, out, b2, N);
}